// round 10
// baseline (speedup 1.0000x reference)
#include <cuda_runtime.h>
#include <cuda_bf16.h>
#include <cstdint>

#define NB 128
#define NN 784
#define NC 512
#define NK 64
#define XSTR 68   // smem row stride (floats): conflict-free frags, 16B rows

// smem float offsets
#define XOFF0 0
#define XOFF1 (128 * XSTR)
#define AOFF0 (2 * 128 * XSTR)
#define AOFF1 (AOFF0 + 64 * XSTR)
#define NRMOFF (AOFF1 + 64 * XSTR)
#define EHOFF (NRMOFF + 128)
#define SMEM_FLOATS (EHOFF + 256)

#define GEMM_GRID 264
#define EPCH 16   // emb_partial n-chunks

// Scratch (no allocations allowed)
__device__ float g_anorm[NK * NC];      // normalized anchors, tf32(rna)-rounded
__device__ float g_A[NB * NN];          // log(sum_k exp(20 s_k)) - 20
__device__ float g_w[NB * NN];          // final weights 2*sigmoid(t)/N
__device__ float g_part[EPCH][NB * NC]; // emb partials per n-chunk

// ------------------------- helpers -----------------------------------------
__device__ __forceinline__ uint32_t f2tf32(float f) {
    uint32_t r;
    asm("cvt.rna.tf32.f32 %0, %1;" : "=r"(r) : "f"(f));
    return r;
}

__device__ __forceinline__ uint32_t smem_u32(const void* p) {
    uint32_t a;
    asm("{ .reg .u64 t; cvta.to.shared.u64 t, %1; cvt.u32.u64 %0, t; }"
        : "=r"(a) : "l"(p));
    return a;
}

__device__ __forceinline__ void cp16(uint32_t dst, const void* src) {
    asm volatile("cp.async.cg.shared.global [%0], [%1], 16;"
                 :: "r"(dst), "l"(src));
}

__device__ __forceinline__ void mma_tf32(float* c, const uint32_t* a, const uint32_t* b) {
    asm("mma.sync.aligned.m16n8k8.row.col.f32.tf32.tf32.f32 "
        "{%0,%1,%2,%3}, {%4,%5,%6,%7}, {%8,%9}, {%0,%1,%2,%3};"
        : "+f"(c[0]), "+f"(c[1]), "+f"(c[2]), "+f"(c[3])
        : "r"(a[0]), "r"(a[1]), "r"(a[2]), "r"(a[3]), "r"(b[0]), "r"(b[1]));
}

// e^x on the FMA/ALU pipes (no MUFU). Valid for |x| <= ~80.
__device__ __forceinline__ float fexp(float x) {
    float y = fmaf(x, 1.4426950408889634f, 12582912.0f);
    float r = y - 12582912.0f;
    float f = fmaf(x, 1.4426950408889634f, -r);
    float p = 1.3387103e-3f;
    p = fmaf(p, f, 9.6183509e-3f);
    p = fmaf(p, f, 5.5504046e-2f);
    p = fmaf(p, f, 2.4022650e-1f);
    p = fmaf(p, f, 6.9314718e-1f);
    p = fmaf(p, f, 1.0f);
    return __int_as_float(__float_as_int(p) + (__float_as_int(y) << 23));
}

// ---------------------------------------------------------------------------
// Kernel 1: normalize anchors (64 rows of 512), store tf32-rounded
// ---------------------------------------------------------------------------
__global__ void anchor_norm_kernel(const float* __restrict__ ker) {
    int k = blockIdx.x;
    int t = threadIdx.x;  // 128
    float s = 0.f;
    float v[4];
#pragma unroll
    for (int i = 0; i < 4; i++) {
        v[i] = ker[k * NC + t + i * 128];
        s += v[i] * v[i];
    }
    __shared__ float red[4];
#pragma unroll
    for (int o = 16; o > 0; o >>= 1) s += __shfl_xor_sync(0xffffffffu, s, o);
    if ((t & 31) == 0) red[t >> 5] = s;
    __syncthreads();
    float tot = red[0] + red[1] + red[2] + red[3];
    float inv = 1.0f / (sqrtf(tot) + 1e-12f);
#pragma unroll
    for (int i = 0; i < 4; i++)
        g_anorm[k * NC + t + i * 128] = __uint_as_float(f2tf32(v[i] * inv));
}

// ---------------------------------------------------------------------------
// Kernel 2: PERSISTENT cp.async-pipelined tf32 mma.sync GEMM.
// Grid 264 x 256: each block owns <=3 M-tiles of 128 rows; the double-buffered
// pipeline runs continuously across tile boundaries (epilogue overlaps the
// next tile's loads). Epilogue = fragment-native logsumexp (no transpose).
// ---------------------------------------------------------------------------
__global__ __launch_bounds__(256) void gemmA_mma(const float* __restrict__ x) {
    extern __shared__ float sm[];
    uint32_t sbase = smem_u32(sm);
    float* snrm = sm + NRMOFF;
    float* eh = sm + EHOFF;  // [2][128] wm-half exp sums

    int t = threadIdx.x;
    int lane = t & 31, w = t >> 5;
    int wm = w >> 2, wn = w & 3;
    int lr = lane >> 2, lc = lane & 3;
    int srow = w * 16 + (lane >> 1);
    int shalf = (lane & 1) * 32;
    int ldrow = t >> 4, ldc4 = (t & 15) * 4;

    int ntile = 0;
    int tlist[3];
    for (int tt = blockIdx.x; tt < NN; tt += GEMM_GRID) tlist[ntile++] = tt;
    int total = ntile * 8;

    float acc[2][4][4];
#pragma unroll
    for (int i = 0; i < 2; i++)
#pragma unroll
        for (int j = 0; j < 4; j++)
#pragma unroll
            for (int q = 0; q < 4; q++) acc[i][j][q] = 0.f;
    float prow = 0.f;

#define LOAD_STAGE(S, TILE, CH)                                                \
    do {                                                                       \
        const float* xc = x + ((size_t)(TILE) * 128) * NC + (CH) * 64;         \
        uint32_t xd = sbase + (((S) ? XOFF1 : XOFF0) + ldrow * XSTR + ldc4) * 4; \
        _Pragma("unroll")                                                      \
        for (int i_ = 0; i_ < 8; i_++)                                         \
            cp16(xd + i_ * 16 * XSTR * 4,                                      \
                 xc + (size_t)(ldrow + 16 * i_) * NC + ldc4);                  \
        const float* ac = g_anorm + (CH) * 64;                                 \
        uint32_t ad = sbase + (((S) ? AOFF1 : AOFF0) + ldrow * XSTR + ldc4) * 4; \
        _Pragma("unroll")                                                      \
        for (int i_ = 0; i_ < 4; i_++)                                         \
            cp16(ad + i_ * 16 * XSTR * 4,                                      \
                 ac + (size_t)(ldrow + 16 * i_) * NC + ldc4);                  \
        asm volatile("cp.async.commit_group;");                                \
    } while (0)

    LOAD_STAGE(0, tlist[0], 0);

    for (int g = 0; g < total; g++) {
        int ch = g & 7;
        if (g + 1 < total) {
            int gn = g + 1;
            LOAD_STAGE(gn & 1, tlist[gn >> 3], gn & 7);
            asm volatile("cp.async.wait_group 1;");
        } else {
            asm volatile("cp.async.wait_group 0;");
        }
        __syncthreads();

        const float* Xs = sm + ((g & 1) ? XOFF1 : XOFF0);
        const float* As = sm + ((g & 1) ? AOFF1 : AOFF0);

        // ---- sumsq on tf32-truncated values (8 LDS.128 per lane) ----
        const uint4* rp = (const uint4*)(Xs + srow * XSTR + shalf);
#pragma unroll
        for (int i = 0; i < 8; i++) {
            uint4 v = rp[i];
            float a0 = __uint_as_float(v.x & 0xFFFFE000u);
            float a1 = __uint_as_float(v.y & 0xFFFFE000u);
            float a2 = __uint_as_float(v.z & 0xFFFFE000u);
            float a3 = __uint_as_float(v.w & 0xFFFFE000u);
            prow = fmaf(a0, a0, prow);
            prow = fmaf(a1, a1, prow);
            prow = fmaf(a2, a2, prow);
            prow = fmaf(a3, a3, prow);
        }

        // ---- MMA: 8 k-steps of k=8 ----
#pragma unroll
        for (int ks = 0; ks < 8; ks++) {
            int c0 = ks * 8;
            uint32_t af[2][4], bf[4][2];
#pragma unroll
            for (int mt = 0; mt < 2; mt++) {
                int ar = wm * 32 + mt * 16 + lr;
                int ac = c0 + lc;
                af[mt][0] = __float_as_uint(As[ar * XSTR + ac]);
                af[mt][1] = __float_as_uint(As[(ar + 8) * XSTR + ac]);
                af[mt][2] = __float_as_uint(As[ar * XSTR + ac + 4]);
                af[mt][3] = __float_as_uint(As[(ar + 8) * XSTR + ac + 4]);
            }
#pragma unroll
            for (int nt = 0; nt < 4; nt++) {
                int br = wn * 32 + nt * 8 + lr;
                int bc = c0 + lc;
                bf[nt][0] = __float_as_uint(Xs[br * XSTR + bc]);
                bf[nt][1] = __float_as_uint(Xs[br * XSTR + bc + 4]);
            }
#pragma unroll
            for (int mt = 0; mt < 2; mt++)
#pragma unroll
                for (int nt = 0; nt < 4; nt++)
                    mma_tf32(acc[mt][nt], af[mt], bf[nt]);
        }
        __syncthreads();  // all reads of this stage done before its reuse

        // ==== tile epilogue (overlaps next tile's in-flight loads) ====
        if (ch == 7) {
            int tile = tlist[g >> 3];
            // publish per-row sumsq
            float pr = prow + __shfl_xor_sync(0xffffffffu, prow, 1);
            if ((lane & 1) == 0) snrm[srow] = pr;
            __syncthreads();

            // fragment-native logsumexp: thread holds 4 k-terms per n
#pragma unroll
            for (int nt = 0; nt < 4; nt++) {
#pragma unroll
                for (int d = 0; d < 2; d++) {
                    int n = wn * 32 + nt * 8 + 2 * lc + d;
                    float sc = 20.f / (sqrtf(snrm[n]) + 1e-12f);
                    float e = fexp(acc[0][nt][d] * sc) + fexp(acc[0][nt][d + 2] * sc)
                            + fexp(acc[1][nt][d] * sc) + fexp(acc[1][nt][d + 2] * sc);
                    // reduce over lr (lanes differing in bits 2..4)
                    e += __shfl_xor_sync(0xffffffffu, e, 4);
                    e += __shfl_xor_sync(0xffffffffu, e, 8);
                    e += __shfl_xor_sync(0xffffffffu, e, 16);
                    if (lr == 0) eh[wm * 128 + n] = e;
                }
            }
            __syncthreads();
            if (t < 128) {
                float sum = eh[t] + eh[128 + t];
                g_A[(size_t)tile * 128 + t] = __logf(sum) - 20.f;
            }
            // reset accumulators for next tile
#pragma unroll
            for (int i = 0; i < 2; i++)
#pragma unroll
                for (int j = 0; j < 4; j++)
#pragma unroll
                    for (int q = 0; q < 4; q++) acc[i][j][q] = 0.f;
            prow = 0.f;
            __syncthreads();  // eh/snrm safe for next tile
        }
    }
}

// ---------------------------------------------------------------------------
// Kernel 3: scalar Sinkhorn solve per batch + final weights
// ---------------------------------------------------------------------------
__global__ void vsolve_kernel() {
    int b = blockIdx.x;
    int t = threadIdx.x;  // 256
    __shared__ float sA[NN];
    __shared__ float red[8];
    for (int i = t; i < NN; i += 256) sA[i] = g_A[b * NN + i];
    __syncthreads();

    float v = 0.f;
    const float invN = 1.f / 784.f;
    for (int s = 0; s < 10; s++) {
        float voe = v * 10.f;  // v / EPS
        float ps = 0.f;
        for (int i = t; i < NN; i += 256) {
            float tt = voe + sA[i];
            ps += 1.f / (1.f + fexp(-tt));
        }
#pragma unroll
        for (int o = 16; o > 0; o >>= 1) ps += __shfl_xor_sync(0xffffffffu, ps, o);
        if ((t & 31) == 0) red[t >> 5] = ps;
        __syncthreads();
        float tot = 0.f;
#pragma unroll
        for (int w = 0; w < 8; w++) tot += red[w];
        float m = logf(tot * invN);
        v += 0.1f * (-0.6931471805599453f - m);
        __syncthreads();
    }
    float voe = v * 10.f;
    for (int i = t; i < NN; i += 256) {
        float tt = voe + sA[i];
        g_w[b * NN + i] = (2.f * invN) / (1.f + fexp(-tt));
    }
}

// ---------------------------------------------------------------------------
// Kernel 4: weighted mean partials, 16 chunks of 49 rows (grid 2048)
// ---------------------------------------------------------------------------
__global__ __launch_bounds__(128) void emb_partial_kernel(const float* __restrict__ x) {
    int rb = (NB * EPCH - 1) - (int)blockIdx.x;  // reverse for L2 tail reuse
    int b = rb >> 4;
    int chk = rb & (EPCH - 1);
    int n0 = chk * 49;
    int t = threadIdx.x;  // 128 threads, one float4 column group each
    __shared__ float sw_[49];
    if (t < 49) sw_[t] = g_w[b * NN + n0 + t];
    __syncthreads();

    const float4* xb = (const float4*)(x + ((size_t)(b * NN + n0)) * NC) + t;
    float ax = 0.f, ay = 0.f, az = 0.f, aw = 0.f;
#pragma unroll 7
    for (int i = 0; i < 49; i++) {
        float w = sw_[i];
        float4 v = xb[(size_t)i * 128];
        ax += w * v.x; ay += w * v.y; az += w * v.z; aw += w * v.w;
    }
    *(float4*)&g_part[chk][b * NC + t * 4] = make_float4(ax, ay, az, aw);
}

// ---------------------------------------------------------------------------
// Kernel 5: deterministic reduction of the 16 partials -> output
// ---------------------------------------------------------------------------
__global__ void emb_reduce_kernel(float* __restrict__ out) {
    int i = blockIdx.x * 256 + threadIdx.x;  // 65536 total
    float s = 0.f;
#pragma unroll
    for (int j = 0; j < EPCH; j++) s += g_part[j][i];
    out[i] = s;
}

// ---------------------------------------------------------------------------
extern "C" void kernel_launch(void* const* d_in, const int* in_sizes, int n_in,
                              void* d_out, int out_size) {
    const float* x = (const float*)d_in[0];    // bow_feats [128,28,28,512]
    const float* ker = (const float*)d_in[1];  // kernel [64,512]
    float* out = (float*)d_out;                // [128,512]

    const int smem = SMEM_FLOATS * 4;
    cudaFuncSetAttribute(gemmA_mma, cudaFuncAttributeMaxDynamicSharedMemorySize, smem);

    anchor_norm_kernel<<<64, 128>>>(ker);
    gemmA_mma<<<GEMM_GRID, 256, smem>>>(x);
    vsolve_kernel<<<NB, 256>>>();
    emb_partial_kernel<<<NB * EPCH, 128>>>(x);
    emb_reduce_kernel<<<(NB * NC) / 256, 256>>>(out);
}

// round 11
// speedup vs baseline: 1.5067x; 1.5067x over previous
#include <cuda_runtime.h>
#include <cuda_bf16.h>
#include <cstdint>

#define NB 128
#define NN 784
#define NC 512
#define NK 64
#define XSTR 68   // smem row stride (floats): conflict-free frags, 16B rows

// smem float offsets
#define XOFF0 0
#define XOFF1 (128 * XSTR)
#define AOFF0 (2 * 128 * XSTR)
#define AOFF1 (AOFF0 + 64 * XSTR)
#define NRMOFF (AOFF1 + 64 * XSTR)
#define EHOFF (NRMOFF + 128)
#define SMEM_FLOATS (EHOFF + 256)

#define EPCH 8    // emb_partial n-chunks

// Scratch (no allocations allowed)
__device__ float g_anorm[NK * NC];      // normalized anchors, tf32(rna)-rounded
__device__ float g_A[NB * NN];          // log(sum_k exp(20 s_k)) - 20
__device__ float g_w[NB * NN];          // final weights 2*sigmoid(t)/N
__device__ float g_part[EPCH][NB * NC]; // emb partials per n-chunk

// ------------------------- helpers -----------------------------------------
__device__ __forceinline__ uint32_t f2tf32(float f) {
    uint32_t r;
    asm("cvt.rna.tf32.f32 %0, %1;" : "=r"(r) : "f"(f));
    return r;
}

__device__ __forceinline__ uint32_t smem_u32(const void* p) {
    uint32_t a;
    asm("{ .reg .u64 t; cvta.to.shared.u64 t, %1; cvt.u32.u64 %0, t; }"
        : "=r"(a) : "l"(p));
    return a;
}

__device__ __forceinline__ void cp16(uint32_t dst, const void* src) {
    asm volatile("cp.async.cg.shared.global [%0], [%1], 16;"
                 :: "r"(dst), "l"(src));
}

__device__ __forceinline__ void mma_tf32(float* c, const uint32_t* a, const uint32_t* b) {
    asm("mma.sync.aligned.m16n8k8.row.col.f32.tf32.tf32.f32 "
        "{%0,%1,%2,%3}, {%4,%5,%6,%7}, {%8,%9}, {%0,%1,%2,%3};"
        : "+f"(c[0]), "+f"(c[1]), "+f"(c[2]), "+f"(c[3])
        : "r"(a[0]), "r"(a[1]), "r"(a[2]), "r"(a[3]), "r"(b[0]), "r"(b[1]));
}

// e^x on the FMA/ALU pipes (no MUFU). Valid for |x| <= ~80.
__device__ __forceinline__ float fexp(float x) {
    float y = fmaf(x, 1.4426950408889634f, 12582912.0f);
    float r = y - 12582912.0f;
    float f = fmaf(x, 1.4426950408889634f, -r);
    float p = 1.3387103e-3f;
    p = fmaf(p, f, 9.6183509e-3f);
    p = fmaf(p, f, 5.5504046e-2f);
    p = fmaf(p, f, 2.4022650e-1f);
    p = fmaf(p, f, 6.9314718e-1f);
    p = fmaf(p, f, 1.0f);
    return __int_as_float(__float_as_int(p) + (__float_as_int(y) << 23));
}

// ---------------------------------------------------------------------------
// Kernel 1: normalize anchors (64 rows of 512), store tf32-rounded
// ---------------------------------------------------------------------------
__global__ void anchor_norm_kernel(const float* __restrict__ ker) {
    int k = blockIdx.x;
    int t = threadIdx.x;  // 128
    float s = 0.f;
    float v[4];
#pragma unroll
    for (int i = 0; i < 4; i++) {
        v[i] = ker[k * NC + t + i * 128];
        s += v[i] * v[i];
    }
    __shared__ float red[4];
#pragma unroll
    for (int o = 16; o > 0; o >>= 1) s += __shfl_xor_sync(0xffffffffu, s, o);
    if ((t & 31) == 0) red[t >> 5] = s;
    __syncthreads();
    float tot = red[0] + red[1] + red[2] + red[3];
    float inv = 1.0f / (sqrtf(tot) + 1e-12f);
#pragma unroll
    for (int i = 0; i < 4; i++)
        g_anorm[k * NC + t + i * 128] = __uint_as_float(f2tf32(v[i] * inv));
}

// ---------------------------------------------------------------------------
// Kernel 2: cp.async double-buffered tf32 mma.sync GEMM.  Grid 784 x 256.
// Sumsq is folded into the B-fragment loads (masked squares on wm==0 warps);
// epilogue is fragment-native logsumexp (no transpose).
// ---------------------------------------------------------------------------
__global__ __launch_bounds__(256) void gemmA_mma(const float* __restrict__ x) {
    extern __shared__ float sm[];
    uint32_t sbase = smem_u32(sm);
    float* snrm = sm + NRMOFF;
    float* eh = sm + EHOFF;  // [2][128] wm-half exp sums

    int t = threadIdx.x;
    int lane = t & 31, w = t >> 5;
    int wm = w >> 2, wn = w & 3;
    int lr = lane >> 2, lc = lane & 3;
    int ldrow = t >> 4, ldc4 = (t & 15) * 4;

    float acc[2][4][4];
#pragma unroll
    for (int i = 0; i < 2; i++)
#pragma unroll
        for (int j = 0; j < 4; j++)
#pragma unroll
            for (int q = 0; q < 4; q++) acc[i][j][q] = 0.f;
    float prow[4] = {0.f, 0.f, 0.f, 0.f};  // per-nt row sumsq partials (wm==0)

    const float* xb = x + (size_t)blockIdx.x * 128 * NC;

#define LOAD_STAGE(S, CH)                                                      \
    do {                                                                       \
        const float* xc = xb + (CH) * 64;                                      \
        uint32_t xd = sbase + (((S) ? XOFF1 : XOFF0) + ldrow * XSTR + ldc4) * 4; \
        _Pragma("unroll")                                                      \
        for (int i_ = 0; i_ < 8; i_++)                                         \
            cp16(xd + i_ * 16 * XSTR * 4,                                      \
                 xc + (size_t)(ldrow + 16 * i_) * NC + ldc4);                  \
        const float* ac = g_anorm + (CH) * 64;                                 \
        uint32_t ad = sbase + (((S) ? AOFF1 : AOFF0) + ldrow * XSTR + ldc4) * 4; \
        _Pragma("unroll")                                                      \
        for (int i_ = 0; i_ < 4; i_++)                                         \
            cp16(ad + i_ * 16 * XSTR * 4,                                      \
                 ac + (size_t)(ldrow + 16 * i_) * NC + ldc4);                  \
        asm volatile("cp.async.commit_group;");                                \
    } while (0)

    LOAD_STAGE(0, 0);

    for (int ch = 0; ch < 8; ch++) {
        if (ch < 7) {
            LOAD_STAGE((ch + 1) & 1, ch + 1);
            asm volatile("cp.async.wait_group 1;");
        } else {
            asm volatile("cp.async.wait_group 0;");
        }
        __syncthreads();

        const float* Xs = sm + ((ch & 1) ? XOFF1 : XOFF0);
        const float* As = sm + ((ch & 1) ? AOFF1 : AOFF0);

        // ---- MMA: 8 k-steps of k=8; sumsq folded into bf loads ----
#pragma unroll
        for (int ks = 0; ks < 8; ks++) {
            int c0 = ks * 8;
            uint32_t af[2][4], bf[4][2];
#pragma unroll
            for (int mt = 0; mt < 2; mt++) {
                int ar = wm * 32 + mt * 16 + lr;
                int ac = c0 + lc;
                af[mt][0] = __float_as_uint(As[ar * XSTR + ac]);
                af[mt][1] = __float_as_uint(As[(ar + 8) * XSTR + ac]);
                af[mt][2] = __float_as_uint(As[ar * XSTR + ac + 4]);
                af[mt][3] = __float_as_uint(As[(ar + 8) * XSTR + ac + 4]);
            }
#pragma unroll
            for (int nt = 0; nt < 4; nt++) {
                int br = wn * 32 + nt * 8 + lr;
                int bc = c0 + lc;
                bf[nt][0] = __float_as_uint(Xs[br * XSTR + bc]);
                bf[nt][1] = __float_as_uint(Xs[br * XSTR + bc + 4]);
            }
            if (wm == 0) {  // warp-uniform: only 4 warps pay the sumsq ALU
#pragma unroll
                for (int nt = 0; nt < 4; nt++) {
                    float m0 = __uint_as_float(bf[nt][0] & 0xFFFFE000u);
                    float m1 = __uint_as_float(bf[nt][1] & 0xFFFFE000u);
                    prow[nt] = fmaf(m0, m0, prow[nt]);
                    prow[nt] = fmaf(m1, m1, prow[nt]);
                }
            }
#pragma unroll
            for (int mt = 0; mt < 2; mt++)
#pragma unroll
                for (int nt = 0; nt < 4; nt++)
                    mma_tf32(acc[mt][nt], af[mt], bf[nt]);
        }
        __syncthreads();  // reads done -> next stage may overwrite this buffer
    }

    // ---- publish per-row sumsq: reduce over the 4-lane lc group ----
    if (wm == 0) {
#pragma unroll
        for (int nt = 0; nt < 4; nt++) {
            float s = prow[nt];
            s += __shfl_xor_sync(0xffffffffu, s, 1);
            s += __shfl_xor_sync(0xffffffffu, s, 2);
            if (lc == 0) snrm[wn * 32 + nt * 8 + lr] = s;
        }
    }
    __syncthreads();

    // ---- fragment-native logsumexp: thread holds 4 k-terms per n ----
#pragma unroll
    for (int nt = 0; nt < 4; nt++) {
#pragma unroll
        for (int d = 0; d < 2; d++) {
            int n = wn * 32 + nt * 8 + 2 * lc + d;
            float sc = 20.f / (sqrtf(snrm[n]) + 1e-12f);
            float e = fexp(acc[0][nt][d] * sc) + fexp(acc[0][nt][d + 2] * sc)
                    + fexp(acc[1][nt][d] * sc) + fexp(acc[1][nt][d + 2] * sc);
            e += __shfl_xor_sync(0xffffffffu, e, 4);
            e += __shfl_xor_sync(0xffffffffu, e, 8);
            e += __shfl_xor_sync(0xffffffffu, e, 16);
            if (lr == 0) eh[wm * 128 + n] = e;
        }
    }
    __syncthreads();
    if (t < 128) {
        float sum = eh[t] + eh[128 + t];
        g_A[(size_t)blockIdx.x * 128 + t] = __logf(sum) - 20.f;
    }
}

// ---------------------------------------------------------------------------
// Kernel 3: scalar Sinkhorn solve per batch + final weights
// ---------------------------------------------------------------------------
__global__ void vsolve_kernel() {
    int b = blockIdx.x;
    int t = threadIdx.x;  // 256
    __shared__ float sA[NN];
    __shared__ float red[8];
    for (int i = t; i < NN; i += 256) sA[i] = g_A[b * NN + i];
    __syncthreads();

    float v = 0.f;
    const float invN = 1.f / 784.f;
    for (int s = 0; s < 10; s++) {
        float voe = v * 10.f;  // v / EPS
        float ps = 0.f;
        for (int i = t; i < NN; i += 256) {
            float tt = voe + sA[i];
            ps += 1.f / (1.f + fexp(-tt));
        }
#pragma unroll
        for (int o = 16; o > 0; o >>= 1) ps += __shfl_xor_sync(0xffffffffu, ps, o);
        if ((t & 31) == 0) red[t >> 5] = ps;
        __syncthreads();
        float tot = 0.f;
#pragma unroll
        for (int w = 0; w < 8; w++) tot += red[w];
        float m = logf(tot * invN);
        v += 0.1f * (-0.6931471805599453f - m);
        __syncthreads();
    }
    float voe = v * 10.f;
    for (int i = t; i < NN; i += 256) {
        float tt = voe + sA[i];
        g_w[b * NN + i] = (2.f * invN) / (1.f + fexp(-tt));
    }
}

// ---------------------------------------------------------------------------
// Kernel 4: weighted mean partials (float4, reversed block order, deep unroll)
// ---------------------------------------------------------------------------
__global__ __launch_bounds__(128) void emb_partial_kernel(const float* __restrict__ x) {
    int rb = (NB * EPCH - 1) - (int)blockIdx.x;  // reverse for L2 tail reuse
    int b = rb >> 3;
    int chk = rb & (EPCH - 1);
    int n0 = chk * 98;
    int t = threadIdx.x;  // 128 threads, one float4 column group each
    __shared__ float sw_[98];
    for (int i = t; i < 98; i += 128) sw_[i] = g_w[b * NN + n0 + i];
    __syncthreads();

    const float4* xb = (const float4*)(x + ((size_t)(b * NN + n0)) * NC) + t;
    float ax = 0.f, ay = 0.f, az = 0.f, aw = 0.f;
#pragma unroll 14
    for (int i = 0; i < 98; i++) {
        float w = sw_[i];
        float4 v = xb[(size_t)i * 128];
        ax += w * v.x; ay += w * v.y; az += w * v.z; aw += w * v.w;
    }
    *(float4*)&g_part[chk][b * NC + t * 4] = make_float4(ax, ay, az, aw);
}

// ---------------------------------------------------------------------------
// Kernel 5: deterministic reduction of the 8 partials -> output
// ---------------------------------------------------------------------------
__global__ void emb_reduce_kernel(float* __restrict__ out) {
    int i = blockIdx.x * 256 + threadIdx.x;  // 65536 total
    float s = 0.f;
#pragma unroll
    for (int j = 0; j < EPCH; j++) s += g_part[j][i];
    out[i] = s;
}

// ---------------------------------------------------------------------------
extern "C" void kernel_launch(void* const* d_in, const int* in_sizes, int n_in,
                              void* d_out, int out_size) {
    const float* x = (const float*)d_in[0];    // bow_feats [128,28,28,512]
    const float* ker = (const float*)d_in[1];  // kernel [64,512]
    float* out = (float*)d_out;                // [128,512]

    const int smem = SMEM_FLOATS * 4;
    cudaFuncSetAttribute(gemmA_mma, cudaFuncAttributeMaxDynamicSharedMemorySize, smem);

    anchor_norm_kernel<<<64, 128>>>(ker);
    gemmA_mma<<<NN, 256, smem>>>(x);
    vsolve_kernel<<<NB, 256>>>();
    emb_partial_kernel<<<NB * EPCH, 128>>>(x);
    emb_reduce_kernel<<<(NB * NC) / 256, 256>>>(out);
}

// round 12
// speedup vs baseline: 1.5392x; 1.0216x over previous
#include <cuda_runtime.h>
#include <cuda_bf16.h>
#include <cstdint>

#define NB 128
#define NN 784
#define NC 512
#define NK 64
#define XSTR 68   // smem row stride (floats): conflict-free frags, 16B rows

// smem float offsets
#define XOFF0 0
#define XOFF1 (128 * XSTR)
#define AOFF0 (2 * 128 * XSTR)     // A stage = 4096 floats (fragment-packed)
#define AOFF1 (AOFF0 + 4096)
#define NRMOFF (AOFF1 + 4096)
#define EHOFF (NRMOFF + 128)
#define SMEM_FLOATS (EHOFF + 256)

#define EPCH 8    // emb_partial n-chunks

// Scratch (no allocations allowed)
__device__ float g_anorm[NK * NC];      // normalized anchors, tf32(rna)-rounded
__device__ float4 g_apack[8192];        // anchors in mma-fragment order
__device__ float g_A[NB * NN];          // log(sum_k exp(20 s_k)) - 20
__device__ float g_w[NB * NN];          // final weights 2*sigmoid(t)/N
__device__ float g_part[EPCH][NB * NC]; // emb partials per n-chunk

// ------------------------- helpers -----------------------------------------
__device__ __forceinline__ uint32_t f2tf32(float f) {
    uint32_t r;
    asm("cvt.rna.tf32.f32 %0, %1;" : "=r"(r) : "f"(f));
    return r;
}

__device__ __forceinline__ uint32_t smem_u32(const void* p) {
    uint32_t a;
    asm("{ .reg .u64 t; cvta.to.shared.u64 t, %1; cvt.u32.u64 %0, t; }"
        : "=r"(a) : "l"(p));
    return a;
}

__device__ __forceinline__ void cp16(uint32_t dst, const void* src) {
    asm volatile("cp.async.cg.shared.global [%0], [%1], 16;"
                 :: "r"(dst), "l"(src));
}

__device__ __forceinline__ void mma_tf32(float* c, const uint32_t* a, const uint32_t* b) {
    asm("mma.sync.aligned.m16n8k8.row.col.f32.tf32.tf32.f32 "
        "{%0,%1,%2,%3}, {%4,%5,%6,%7}, {%8,%9}, {%0,%1,%2,%3};"
        : "+f"(c[0]), "+f"(c[1]), "+f"(c[2]), "+f"(c[3])
        : "r"(a[0]), "r"(a[1]), "r"(a[2]), "r"(a[3]), "r"(b[0]), "r"(b[1]));
}

// e^x on the FMA/ALU pipes (no MUFU). Valid for |x| <= ~80.
__device__ __forceinline__ float fexp(float x) {
    float y = fmaf(x, 1.4426950408889634f, 12582912.0f);
    float r = y - 12582912.0f;
    float f = fmaf(x, 1.4426950408889634f, -r);
    float p = 1.3387103e-3f;
    p = fmaf(p, f, 9.6183509e-3f);
    p = fmaf(p, f, 5.5504046e-2f);
    p = fmaf(p, f, 2.4022650e-1f);
    p = fmaf(p, f, 6.9314718e-1f);
    p = fmaf(p, f, 1.0f);
    return __int_as_float(__float_as_int(p) + (__float_as_int(y) << 23));
}

// ---------------------------------------------------------------------------
// Kernel 1: normalize anchors (64 rows of 512), store tf32-rounded
// ---------------------------------------------------------------------------
__global__ void anchor_norm_kernel(const float* __restrict__ ker) {
    int k = blockIdx.x;
    int t = threadIdx.x;  // 128
    float s = 0.f;
    float v[4];
#pragma unroll
    for (int i = 0; i < 4; i++) {
        v[i] = ker[k * NC + t + i * 128];
        s += v[i] * v[i];
    }
    __shared__ float red[4];
#pragma unroll
    for (int o = 16; o > 0; o >>= 1) s += __shfl_xor_sync(0xffffffffu, s, o);
    if ((t & 31) == 0) red[t >> 5] = s;
    __syncthreads();
    float tot = red[0] + red[1] + red[2] + red[3];
    float inv = 1.0f / (sqrtf(tot) + 1e-12f);
#pragma unroll
    for (int i = 0; i < 4; i++)
        g_anorm[k * NC + t + i * 128] = __uint_as_float(f2tf32(v[i] * inv));
}

// ---------------------------------------------------------------------------
// Kernel 1b: pack anchors into mma-fragment order.
// Entry i = (((ch*8 + ks)*2 + h)*2 + mt)*32 + lane holds this lane's 4 A-regs.
// ---------------------------------------------------------------------------
__global__ void anchor_pack_kernel() {
    int i = blockIdx.x * 256 + threadIdx.x;  // 8192
    int lane = i & 31, mt = (i >> 5) & 1, h = (i >> 6) & 1;
    int ks = (i >> 7) & 7, ch = i >> 10;
    int r0 = h * 32 + mt * 16 + (lane >> 2);
    int c0 = ch * 64 + ks * 8 + (lane & 3);
    float4 v;
    v.x = g_anorm[r0 * NC + c0];
    v.y = g_anorm[(r0 + 8) * NC + c0];
    v.z = g_anorm[r0 * NC + c0 + 4];
    v.w = g_anorm[(r0 + 8) * NC + c0 + 4];
    g_apack[i] = v;
}

// ---------------------------------------------------------------------------
// Kernel 2: cp.async double-buffered tf32 mma.sync GEMM.  Grid 784 x 256.
// A fragments come pre-packed: 1 LDS.128 per (ks, mt). Sumsq folded into the
// B-fragment loads (wm==0 warps); fragment-native logsumexp epilogue.
// ---------------------------------------------------------------------------
__global__ __launch_bounds__(256) void gemmA_mma(const float* __restrict__ x) {
    extern __shared__ float sm[];
    uint32_t sbase = smem_u32(sm);
    float* snrm = sm + NRMOFF;
    float* eh = sm + EHOFF;  // [2][128] wm-half exp sums

    int t = threadIdx.x;
    int lane = t & 31, w = t >> 5;
    int wm = w >> 2, wn = w & 3;
    int lr = lane >> 2, lc = lane & 3;
    int ldrow = t >> 4, ldc4 = (t & 15) * 4;

    float acc[2][4][4];
#pragma unroll
    for (int i = 0; i < 2; i++)
#pragma unroll
        for (int j = 0; j < 4; j++)
#pragma unroll
            for (int q = 0; q < 4; q++) acc[i][j][q] = 0.f;
    float prow[4] = {0.f, 0.f, 0.f, 0.f};  // per-nt row sumsq partials (wm==0)

    const float* xb = x + (size_t)blockIdx.x * 128 * NC;

#define LOAD_STAGE(S, CH)                                                      \
    do {                                                                       \
        const float* xc = xb + (CH) * 64;                                      \
        uint32_t xd = sbase + (((S) ? XOFF1 : XOFF0) + ldrow * XSTR + ldc4) * 4; \
        _Pragma("unroll")                                                      \
        for (int i_ = 0; i_ < 8; i_++)                                         \
            cp16(xd + i_ * 16 * XSTR * 4,                                      \
                 xc + (size_t)(ldrow + 16 * i_) * NC + ldc4);                  \
        const float4* ap = g_apack + (CH) * 1024 + t;                          \
        uint32_t ad = sbase + ((S) ? AOFF1 : AOFF0) * 4 + t * 16;              \
        _Pragma("unroll")                                                      \
        for (int i_ = 0; i_ < 4; i_++)                                         \
            cp16(ad + i_ * 4096, ap + i_ * 256);                               \
        asm volatile("cp.async.commit_group;");                                \
    } while (0)

    LOAD_STAGE(0, 0);

    for (int ch = 0; ch < 8; ch++) {
        if (ch < 7) {
            LOAD_STAGE((ch + 1) & 1, ch + 1);
            asm volatile("cp.async.wait_group 1;");
        } else {
            asm volatile("cp.async.wait_group 0;");
        }
        __syncthreads();

        const float* Xs = sm + ((ch & 1) ? XOFF1 : XOFF0);
        const uint4* Af = (const uint4*)(sm + ((ch & 1) ? AOFF1 : AOFF0));

        // ---- MMA: 8 k-steps of k=8; af = 2x LDS.128, sumsq folded in ----
#pragma unroll
        for (int ks = 0; ks < 8; ks++) {
            int c0 = ks * 8;
            uint4 a0 = Af[((ks * 2 + wm) * 2 + 0) * 32 + lane];
            uint4 a1 = Af[((ks * 2 + wm) * 2 + 1) * 32 + lane];
            uint32_t af[2][4] = {{a0.x, a0.y, a0.z, a0.w},
                                 {a1.x, a1.y, a1.z, a1.w}};
            uint32_t bf[4][2];
#pragma unroll
            for (int nt = 0; nt < 4; nt++) {
                int br = wn * 32 + nt * 8 + lr;
                int bc = c0 + lc;
                bf[nt][0] = __float_as_uint(Xs[br * XSTR + bc]);
                bf[nt][1] = __float_as_uint(Xs[br * XSTR + bc + 4]);
            }
            if (wm == 0) {  // warp-uniform: only 4 warps pay the sumsq ALU
#pragma unroll
                for (int nt = 0; nt < 4; nt++) {
                    float m0 = __uint_as_float(bf[nt][0] & 0xFFFFE000u);
                    float m1 = __uint_as_float(bf[nt][1] & 0xFFFFE000u);
                    prow[nt] = fmaf(m0, m0, prow[nt]);
                    prow[nt] = fmaf(m1, m1, prow[nt]);
                }
            }
#pragma unroll
            for (int mt = 0; mt < 2; mt++)
#pragma unroll
                for (int nt = 0; nt < 4; nt++)
                    mma_tf32(acc[mt][nt], af[mt], bf[nt]);
        }
        __syncthreads();  // reads done -> next stage may overwrite this buffer
    }

    // ---- publish per-row sumsq: reduce over the 4-lane lc group ----
    if (wm == 0) {
#pragma unroll
        for (int nt = 0; nt < 4; nt++) {
            float s = prow[nt];
            s += __shfl_xor_sync(0xffffffffu, s, 1);
            s += __shfl_xor_sync(0xffffffffu, s, 2);
            if (lc == 0) snrm[wn * 32 + nt * 8 + lr] = s;
        }
    }
    __syncthreads();

    // ---- fragment-native logsumexp: thread holds 4 k-terms per n ----
#pragma unroll
    for (int nt = 0; nt < 4; nt++) {
#pragma unroll
        for (int d = 0; d < 2; d++) {
            int n = wn * 32 + nt * 8 + 2 * lc + d;
            float sc = 20.f / (sqrtf(snrm[n]) + 1e-12f);
            float e = fexp(acc[0][nt][d] * sc) + fexp(acc[0][nt][d + 2] * sc)
                    + fexp(acc[1][nt][d] * sc) + fexp(acc[1][nt][d + 2] * sc);
            e += __shfl_xor_sync(0xffffffffu, e, 4);
            e += __shfl_xor_sync(0xffffffffu, e, 8);
            e += __shfl_xor_sync(0xffffffffu, e, 16);
            if (lr == 0) eh[wm * 128 + n] = e;
        }
    }
    __syncthreads();
    if (t < 128) {
        float sum = eh[t] + eh[128 + t];
        g_A[(size_t)blockIdx.x * 128 + t] = __logf(sum) - 20.f;
    }
}

// ---------------------------------------------------------------------------
// Kernel 3: scalar Sinkhorn solve per batch + final weights
// ---------------------------------------------------------------------------
__global__ void vsolve_kernel() {
    int b = blockIdx.x;
    int t = threadIdx.x;  // 256
    __shared__ float sA[NN];
    __shared__ float red[8];
    for (int i = t; i < NN; i += 256) sA[i] = g_A[b * NN + i];
    __syncthreads();

    float v = 0.f;
    const float invN = 1.f / 784.f;
    for (int s = 0; s < 10; s++) {
        float voe = v * 10.f;  // v / EPS
        float ps = 0.f;
        for (int i = t; i < NN; i += 256) {
            float tt = voe + sA[i];
            ps += 1.f / (1.f + fexp(-tt));
        }
#pragma unroll
        for (int o = 16; o > 0; o >>= 1) ps += __shfl_xor_sync(0xffffffffu, ps, o);
        if ((t & 31) == 0) red[t >> 5] = ps;
        __syncthreads();
        float tot = 0.f;
#pragma unroll
        for (int w = 0; w < 8; w++) tot += red[w];
        float m = logf(tot * invN);
        v += 0.1f * (-0.6931471805599453f - m);
        __syncthreads();
    }
    float voe = v * 10.f;
    for (int i = t; i < NN; i += 256) {
        float tt = voe + sA[i];
        g_w[b * NN + i] = (2.f * invN) / (1.f + fexp(-tt));
    }
}

// ---------------------------------------------------------------------------
// Kernel 4: weighted mean partials (float4, reversed block order, deep unroll)
// ---------------------------------------------------------------------------
__global__ __launch_bounds__(128) void emb_partial_kernel(const float* __restrict__ x) {
    int rb = (NB * EPCH - 1) - (int)blockIdx.x;  // reverse for L2 tail reuse
    int b = rb >> 3;
    int chk = rb & (EPCH - 1);
    int n0 = chk * 98;
    int t = threadIdx.x;  // 128 threads, one float4 column group each
    __shared__ float sw_[98];
    for (int i = t; i < 98; i += 128) sw_[i] = g_w[b * NN + n0 + i];
    __syncthreads();

    const float4* xb = (const float4*)(x + ((size_t)(b * NN + n0)) * NC) + t;
    float ax = 0.f, ay = 0.f, az = 0.f, aw = 0.f;
#pragma unroll 14
    for (int i = 0; i < 98; i++) {
        float w = sw_[i];
        float4 v = xb[(size_t)i * 128];
        ax += w * v.x; ay += w * v.y; az += w * v.z; aw += w * v.w;
    }
    *(float4*)&g_part[chk][b * NC + t * 4] = make_float4(ax, ay, az, aw);
}

// ---------------------------------------------------------------------------
// Kernel 5: deterministic reduction of the 8 partials -> output
// ---------------------------------------------------------------------------
__global__ void emb_reduce_kernel(float* __restrict__ out) {
    int i = blockIdx.x * 256 + threadIdx.x;  // 65536 total
    float s = 0.f;
#pragma unroll
    for (int j = 0; j < EPCH; j++) s += g_part[j][i];
    out[i] = s;
}

// ---------------------------------------------------------------------------
extern "C" void kernel_launch(void* const* d_in, const int* in_sizes, int n_in,
                              void* d_out, int out_size) {
    const float* x = (const float*)d_in[0];    // bow_feats [128,28,28,512]
    const float* ker = (const float*)d_in[1];  // kernel [64,512]
    float* out = (float*)d_out;                // [128,512]

    const int smem = SMEM_FLOATS * 4;
    cudaFuncSetAttribute(gemmA_mma, cudaFuncAttributeMaxDynamicSharedMemorySize, smem);

    anchor_norm_kernel<<<64, 128>>>(ker);
    anchor_pack_kernel<<<32, 256>>>();
    gemmA_mma<<<NN, 256, smem>>>(x);
    vsolve_kernel<<<NB, 256>>>();
    emb_partial_kernel<<<NB * EPCH, 128>>>(x);
    emb_reduce_kernel<<<(NB * NC) / 256, 256>>>(out);
}

// round 13
// speedup vs baseline: 1.5430x; 1.0024x over previous
#include <cuda_runtime.h>
#include <cstdint>

#define NB 128
#define NN 784
#define NC 512
#define NK 64
#define XSTR 36        // smem row stride (floats) for 32-col X tiles

// gemm smem float offsets: 4 X stages, 4 A stages
#define XOFF(s) ((s) * 128 * XSTR)
#define AOFF(s) (4 * 128 * XSTR + (s) * 2048)
#define NRMOFF (4 * 128 * XSTR + 4 * 2048)
#define EHOFF (NRMOFF + 128)
#define SMEM_FLOATS (EHOFF + 256)

#define EPCH 8    // emb_partial n-chunks

// Scratch (no allocations allowed)
__device__ float g_anorm[NK * NC];      // normalized anchors, tf32(rna)-rounded
__device__ float4 g_apack[8192];        // anchors in mma-fragment order
__device__ float g_A[NB * NN];          // log(sum_k exp(20 s_k)) - 20
__device__ float g_w[NB * NN];          // final weights 2*sigmoid(t)/N
__device__ float g_part[EPCH][NB * NC]; // emb partials per n-chunk

// ------------------------- helpers -----------------------------------------
__device__ __forceinline__ uint32_t f2tf32(float f) {
    uint32_t r;
    asm("cvt.rna.tf32.f32 %0, %1;" : "=r"(r) : "f"(f));
    return r;
}

__device__ __forceinline__ uint32_t smem_u32(const void* p) {
    uint32_t a;
    asm("{ .reg .u64 t; cvta.to.shared.u64 t, %1; cvt.u32.u64 %0, t; }"
        : "=r"(a) : "l"(p));
    return a;
}

__device__ __forceinline__ void cp16(uint32_t dst, const void* src) {
    asm volatile("cp.async.cg.shared.global [%0], [%1], 16;"
                 :: "r"(dst), "l"(src));
}

__device__ __forceinline__ void mma_tf32(float* c, const uint32_t* a, const uint32_t* b) {
    asm("mma.sync.aligned.m16n8k8.row.col.f32.tf32.tf32.f32 "
        "{%0,%1,%2,%3}, {%4,%5,%6,%7}, {%8,%9}, {%0,%1,%2,%3};"
        : "+f"(c[0]), "+f"(c[1]), "+f"(c[2]), "+f"(c[3])
        : "r"(a[0]), "r"(a[1]), "r"(a[2]), "r"(a[3]), "r"(b[0]), "r"(b[1]));
}

// e^x on the FMA/ALU pipes (no MUFU). Valid for |x| <= ~80.
__device__ __forceinline__ float fexp(float x) {
    float y = fmaf(x, 1.4426950408889634f, 12582912.0f);
    float r = y - 12582912.0f;
    float f = fmaf(x, 1.4426950408889634f, -r);
    float p = 1.3387103e-3f;
    p = fmaf(p, f, 9.6183509e-3f);
    p = fmaf(p, f, 5.5504046e-2f);
    p = fmaf(p, f, 2.4022650e-1f);
    p = fmaf(p, f, 6.9314718e-1f);
    p = fmaf(p, f, 1.0f);
    return __int_as_float(__float_as_int(p) + (__float_as_int(y) << 23));
}

// ---------------------------------------------------------------------------
// Kernel 1: normalize anchors (64 rows of 512), store tf32-rounded
// ---------------------------------------------------------------------------
__global__ void anchor_norm_kernel(const float* __restrict__ ker) {
    int k = blockIdx.x;
    int t = threadIdx.x;  // 128
    float s = 0.f;
    float v[4];
#pragma unroll
    for (int i = 0; i < 4; i++) {
        v[i] = ker[k * NC + t + i * 128];
        s += v[i] * v[i];
    }
    __shared__ float red[4];
#pragma unroll
    for (int o = 16; o > 0; o >>= 1) s += __shfl_xor_sync(0xffffffffu, s, o);
    if ((t & 31) == 0) red[t >> 5] = s;
    __syncthreads();
    float tot = red[0] + red[1] + red[2] + red[3];
    float inv = 1.0f / (sqrtf(tot) + 1e-12f);
#pragma unroll
    for (int i = 0; i < 4; i++)
        g_anorm[k * NC + t + i * 128] = __uint_as_float(f2tf32(v[i] * inv));
}

// ---------------------------------------------------------------------------
// Kernel 1b: pack anchors into mma-fragment order.
// Entry i = ((col8*2 + h)*2 + mt)*32 + lane holds that lane's 4 A-regs.
// ---------------------------------------------------------------------------
__global__ void anchor_pack_kernel() {
    int i = blockIdx.x * 256 + threadIdx.x;  // 8192
    int lane = i & 31, mt = (i >> 5) & 1, h = (i >> 6) & 1;
    int col8 = i >> 7;  // global k-step 0..63
    int r0 = h * 32 + mt * 16 + (lane >> 2);
    int c0 = col8 * 8 + (lane & 3);
    float4 v;
    v.x = g_anorm[r0 * NC + c0];
    v.y = g_anorm[(r0 + 8) * NC + c0];
    v.z = g_anorm[r0 * NC + c0 + 4];
    v.w = g_anorm[(r0 + 8) * NC + c0 + 4];
    g_apack[i] = v;
}

// ---------------------------------------------------------------------------
// Kernel 2: 4-stage cp.async pipelined tf32 mma.sync GEMM. Grid 784 x 256.
// 16 K-chunks of 32 cols; A fragments pre-packed (LDS.128); sumsq folded into
// B-fragment loads (wm==0 warps); fragment-native logsumexp epilogue.
// ---------------------------------------------------------------------------
__global__ __launch_bounds__(256) void gemmA_mma(const float* __restrict__ x) {
    extern __shared__ float sm[];
    uint32_t sbase = smem_u32(sm);
    float* snrm = sm + NRMOFF;
    float* eh = sm + EHOFF;  // [2][128] wm-half exp sums

    int t = threadIdx.x;
    int lane = t & 31, w = t >> 5;
    int wm = w >> 2, wn = w & 3;
    int lr = lane >> 2, lc = lane & 3;
    int ldrow = t >> 3, ldc4 = (t & 7) * 4;

    float acc[2][4][4];
#pragma unroll
    for (int i = 0; i < 2; i++)
#pragma unroll
        for (int j = 0; j < 4; j++)
#pragma unroll
            for (int q = 0; q < 4; q++) acc[i][j][q] = 0.f;
    float prow[4] = {0.f, 0.f, 0.f, 0.f};  // per-nt row sumsq partials (wm==0)

    const float* xb = x + (size_t)blockIdx.x * 128 * NC;

#define LOAD_STAGE(S, CH)                                                      \
    do {                                                                       \
        const float* xc = xb + (CH) * 32;                                      \
        uint32_t xd = sbase + (XOFF(S) + ldrow * XSTR + ldc4) * 4;             \
        _Pragma("unroll")                                                      \
        for (int i_ = 0; i_ < 4; i_++)                                         \
            cp16(xd + i_ * 32 * XSTR * 4,                                      \
                 xc + (size_t)(ldrow + 32 * i_) * NC + ldc4);                  \
        const float4* ap = g_apack + (CH) * 512 + t;                           \
        uint32_t ad = sbase + AOFF(S) * 4 + t * 16;                            \
        cp16(ad, ap);                                                          \
        cp16(ad + 4096, ap + 256);                                             \
        asm volatile("cp.async.commit_group;");                                \
    } while (0)

    LOAD_STAGE(0, 0);
    LOAD_STAGE(1, 1);
    LOAD_STAGE(2, 2);

    for (int ch = 0; ch < 16; ch++) {
        int st = ch & 3;
        if (ch < 13) {
            LOAD_STAGE((ch + 3) & 3, ch + 3);
            asm volatile("cp.async.wait_group 3;");
        } else if (ch == 13) {
            asm volatile("cp.async.wait_group 2;");
        } else if (ch == 14) {
            asm volatile("cp.async.wait_group 1;");
        } else {
            asm volatile("cp.async.wait_group 0;");
        }
        __syncthreads();

        const float* Xs = sm + XOFF(st);
        const uint4* Af = (const uint4*)(sm + AOFF(st));

        // ---- MMA: 4 k-steps of k=8; af = 2x LDS.128, sumsq folded in ----
#pragma unroll
        for (int ks = 0; ks < 4; ks++) {
            int c0 = ks * 8;
            uint4 a0 = Af[((ks * 2 + wm) * 2 + 0) * 32 + lane];
            uint4 a1 = Af[((ks * 2 + wm) * 2 + 1) * 32 + lane];
            uint32_t af[2][4] = {{a0.x, a0.y, a0.z, a0.w},
                                 {a1.x, a1.y, a1.z, a1.w}};
            uint32_t bf[4][2];
#pragma unroll
            for (int nt = 0; nt < 4; nt++) {
                int br = wn * 32 + nt * 8 + lr;
                int bc = c0 + lc;
                bf[nt][0] = __float_as_uint(Xs[br * XSTR + bc]);
                bf[nt][1] = __float_as_uint(Xs[br * XSTR + bc + 4]);
            }
            if (wm == 0) {  // warp-uniform: only 4 warps pay the sumsq ALU
#pragma unroll
                for (int nt = 0; nt < 4; nt++) {
                    float m0 = __uint_as_float(bf[nt][0] & 0xFFFFE000u);
                    float m1 = __uint_as_float(bf[nt][1] & 0xFFFFE000u);
                    prow[nt] = fmaf(m0, m0, prow[nt]);
                    prow[nt] = fmaf(m1, m1, prow[nt]);
                }
            }
#pragma unroll
            for (int mt = 0; mt < 2; mt++)
#pragma unroll
                for (int nt = 0; nt < 4; nt++)
                    mma_tf32(acc[mt][nt], af[mt], bf[nt]);
        }
        __syncthreads();  // reads done -> stage reusable by later loads
    }

    // ---- publish per-row sumsq: reduce over the 4-lane lc group ----
    if (wm == 0) {
#pragma unroll
        for (int nt = 0; nt < 4; nt++) {
            float s = prow[nt];
            s += __shfl_xor_sync(0xffffffffu, s, 1);
            s += __shfl_xor_sync(0xffffffffu, s, 2);
            if (lc == 0) snrm[wn * 32 + nt * 8 + lr] = s;
        }
    }
    __syncthreads();

    // ---- fragment-native logsumexp: thread holds 4 k-terms per n ----
#pragma unroll
    for (int nt = 0; nt < 4; nt++) {
#pragma unroll
        for (int d = 0; d < 2; d++) {
            int n = wn * 32 + nt * 8 + 2 * lc + d;
            float sc = 20.f / (sqrtf(snrm[n]) + 1e-12f);
            float e = fexp(acc[0][nt][d] * sc) + fexp(acc[0][nt][d + 2] * sc)
                    + fexp(acc[1][nt][d] * sc) + fexp(acc[1][nt][d + 2] * sc);
            e += __shfl_xor_sync(0xffffffffu, e, 4);
            e += __shfl_xor_sync(0xffffffffu, e, 8);
            e += __shfl_xor_sync(0xffffffffu, e, 16);
            if (lr == 0) eh[wm * 128 + n] = e;
        }
    }
    __syncthreads();
    if (t < 128) {
        float sum = eh[t] + eh[128 + t];
        g_A[(size_t)blockIdx.x * 128 + t] = __logf(sum) - 20.f;
    }
}

// ---------------------------------------------------------------------------
// Kernel 3: scalar Sinkhorn solve per batch + final weights.
// A in registers, one barrier per iteration (double-buffered reduction).
// ---------------------------------------------------------------------------
__global__ void vsolve_kernel() {
    int b = blockIdx.x;
    int t = threadIdx.x;  // 256
    int lane = t & 31, wid = t >> 5;
    __shared__ float red[2][8];

    const float* Ab = g_A + b * NN;
    float a0 = Ab[t], a1 = Ab[t + 256], a2 = Ab[t + 512];
    float a3 = (t < 16) ? Ab[t + 768] : 0.f;

    float v = 0.f;
    for (int s = 0; s < 10; s++) {
        float voe = v * 10.f;  // v / EPS
        float ps = 1.f / (1.f + fexp(-(voe + a0)))
                 + 1.f / (1.f + fexp(-(voe + a1)))
                 + 1.f / (1.f + fexp(-(voe + a2)));
        if (t < 16) ps += 1.f / (1.f + fexp(-(voe + a3)));
#pragma unroll
        for (int o = 16; o > 0; o >>= 1) ps += __shfl_xor_sync(0xffffffffu, ps, o);
        if (lane == 0) red[s & 1][wid] = ps;
        __syncthreads();
        float tot = red[s & 1][0] + red[s & 1][1] + red[s & 1][2] + red[s & 1][3]
                  + red[s & 1][4] + red[s & 1][5] + red[s & 1][6] + red[s & 1][7];
        // m = log(tot/784); v += eps*(log(mu) - m);  log(784)=6.664409020350408
        v += 0.1f * (-0.6931471805599453f - (__logf(tot) - 6.664409020350408f));
    }
    float voe = v * 10.f;
    const float c = 2.f / 784.f;
    g_w[b * NN + t] = c / (1.f + fexp(-(voe + a0)));
    g_w[b * NN + t + 256] = c / (1.f + fexp(-(voe + a1)));
    g_w[b * NN + t + 512] = c / (1.f + fexp(-(voe + a2)));
    if (t < 16) g_w[b * NN + t + 768] = c / (1.f + fexp(-(voe + a3)));
}

// ---------------------------------------------------------------------------
// Kernel 4: weighted mean partials (float4, reversed block order, deep unroll)
// ---------------------------------------------------------------------------
__global__ __launch_bounds__(128) void emb_partial_kernel(const float* __restrict__ x) {
    int rb = (NB * EPCH - 1) - (int)blockIdx.x;  // reverse for L2 tail reuse
    int b = rb >> 3;
    int chk = rb & (EPCH - 1);
    int n0 = chk * 98;
    int t = threadIdx.x;  // 128 threads, one float4 column group each
    __shared__ float sw_[98];
    for (int i = t; i < 98; i += 128) sw_[i] = g_w[b * NN + n0 + i];
    __syncthreads();

    const float4* xb = (const float4*)(x + ((size_t)(b * NN + n0)) * NC) + t;
    float ax = 0.f, ay = 0.f, az = 0.f, aw = 0.f;
#pragma unroll 14
    for (int i = 0; i < 98; i++) {
        float w = sw_[i];
        float4 v = xb[(size_t)i * 128];
        ax += w * v.x; ay += w * v.y; az += w * v.z; aw += w * v.w;
    }
    *(float4*)&g_part[chk][b * NC + t * 4] = make_float4(ax, ay, az, aw);
}

// ---------------------------------------------------------------------------
// Kernel 5: deterministic reduction of the 8 partials -> output
// ---------------------------------------------------------------------------
__global__ void emb_reduce_kernel(float* __restrict__ out) {
    int i = blockIdx.x * 256 + threadIdx.x;  // 65536 total
    float s = 0.f;
#pragma unroll
    for (int j = 0; j < EPCH; j++) s += g_part[j][i];
    out[i] = s;
}

// ---------------------------------------------------------------------------
extern "C" void kernel_launch(void* const* d_in, const int* in_sizes, int n_in,
                              void* d_out, int out_size) {
    const float* x = (const float*)d_in[0];    // bow_feats [128,28,28,512]
    const float* ker = (const float*)d_in[1];  // kernel [64,512]
    float* out = (float*)d_out;                // [128,512]

    const int smem = SMEM_FLOATS * 4;  // 108032 B
    cudaFuncSetAttribute(gemmA_mma, cudaFuncAttributeMaxDynamicSharedMemorySize, smem);

    anchor_norm_kernel<<<64, 128>>>(ker);
    anchor_pack_kernel<<<32, 256>>>();
    gemmA_mma<<<NN, 256, smem>>>(x);
    vsolve_kernel<<<NB, 256>>>();
    emb_partial_kernel<<<NB * EPCH, 128>>>(x);
    emb_reduce_kernel<<<(NB * NC) / 256, 256>>>(out);
}